// round 6
// baseline (speedup 1.0000x reference)
#include <cuda_runtime.h>

// LocSE fused kernel for GB300.
// Shapes (fixed): B=4, N=16384, DIMS=2, K1=17, UNITS=128, CH=53.
// Factorization: the (17 x 53) @ (53 x 64) per-neighborhood matmul
// = one shared 34-dim projection S[u] + a rank-3 per-j term.
// R6: one STG.128 per lane per output row (lanes 0-15 = feats float4,
// lanes 16-31 = 4 relu channels), 32-bit address math, feats LDG pipelined.

#define NPTS   16384
#define BN     65536          // B*N
#define K1V    17
#define WARPS  8
#define OUT_FLOATS_PER_G 2176 // 17*128

__global__ __launch_bounds__(256, 6)
void locse_kernel(const float2* __restrict__ pc,      // (B,N) float2
                  const float4* __restrict__ feats,   // (B,N,16) float4 (64 floats)
                  const int*    __restrict__ nidx,    // (B,N,17)
                  const float*  __restrict__ W,       // (53,64)
                  const float*  __restrict__ bvec,    // (64,)
                  float4*       __restrict__ out,     // (B,N,17,32) float4
                  float2*       __restrict__ ggf)     // (B,N,1,2) as float2
{
    // sW[c*64 + u] = W[(2 + 3*(c>>1) + (c&1))*64 + u], c = 2i+d, i<17, d<2
    __shared__ __align__(16) float sW[34 * 64];
    __shared__ __align__(16) float sWx[64], sWy[64], sWn[64], sB[64];
    __shared__ float4 pts[WARPS][K1V];   // (x, y, norm, idx_as_float)

    const int tid = threadIdx.x;

    // ---- stage derived weights (once per block) ----
    if (tid < 64) {
        const int u = tid;
        float wx = W[u];          // W[0][u]
        float wy = W[64 + u];     // W[1][u]
        float wn = 0.f;
        #pragma unroll
        for (int i = 0; i < K1V; i++) {
            wx -= W[(2 + 3 * i) * 64 + u];
            wy -= W[(3 + 3 * i) * 64 + u];
            wn += W[(4 + 3 * i) * 64 + u];
        }
        sWx[u] = wx; sWy[u] = wy; sWn[u] = wn; sB[u] = bvec[u];
    }
    #pragma unroll 1
    for (int t = tid; t < 34 * 64; t += 256) {
        const int c = t >> 6, u = t & 63;
        const int i = c >> 1, d = c & 1;
        sW[t] = W[(2 + 3 * i + d) * 64 + u];
    }
    __syncthreads();

    const int lane = tid & 31, warp = tid >> 5;
    const unsigned g = blockIdx.x * WARPS + warp;   // neighborhood id in [0, BN)
    const unsigned b = g >> 14;                     // g / 16384
    const int* __restrict__ ip = nidx + (size_t)g * K1V;

    // ---- phase A: gather 17 points, norms ----
    float x = 0.f, y = 0.f;
    if (lane < K1V) {
        const int ii = ip[lane];
        const float2 p = pc[(size_t)b * NPTS + ii];
        x = p.x; y = p.y;
        const float nrm = sqrtf(x * x + y * y);
        pts[warp][lane] = make_float4(x, y, nrm, __int_as_float(ii));
    }
    __syncwarp();

    // ---- ggf: two-pass centered stats over 17 points (matches reference) ----
    float sx = x, sy = y;
    #pragma unroll
    for (int o = 16; o; o >>= 1) {
        sx += __shfl_xor_sync(0xffffffffu, sx, o);
        sy += __shfl_xor_sync(0xffffffffu, sy, o);
    }
    const float inv17 = 1.0f / 17.0f;
    const float mx = sx * inv17, my = sy * inv17;
    const float xc = (lane < K1V) ? (x - mx) : 0.f;
    const float yc = (lane < K1V) ? (y - my) : 0.f;
    float sxx = xc * xc, syy = yc * yc, sxy = xc * yc;
    #pragma unroll
    for (int o = 16; o; o >>= 1) {
        sxx += __shfl_xor_sync(0xffffffffu, sxx, o);
        syy += __shfl_xor_sync(0xffffffffu, syy, o);
        sxy += __shfl_xor_sync(0xffffffffu, sxy, o);
    }
    if (lane == 0) {
        const float vx = sxx * inv17, vy = syy * inv17, cov = sxy * inv17;
        const float m    = cov / (vx + 1e-8f);
        const float pear = cov / (sqrtf(vx * vy) + 1e-8f);
        __stcs(ggf + g, make_float2(m, 1.0f - pear));
    }

    // ---- phase B: shared projection (upper 16 lanes own 4 channels each) ----
    const bool mlp = (lane >= 16);
    const int u4 = (lane & 15) * 4;   // channel group for upper lanes
    float4 acc = make_float4(0.f, 0.f, 0.f, 0.f);
    float4 wx4, wy4, wn4;
    if (mlp) {
        acc = *(const float4*)&sB[u4];
        #pragma unroll
        for (int i = 0; i < K1V; i++) {
            const float4 pt  = pts[warp][i];                    // LDS broadcast
            const float4 wxv = *(const float4*)&sW[(2 * i) * 64 + u4];
            const float4 wyv = *(const float4*)&sW[(2 * i + 1) * 64 + u4];
            acc.x = fmaf(pt.x, wxv.x, fmaf(pt.y, wyv.x, acc.x));
            acc.y = fmaf(pt.x, wxv.y, fmaf(pt.y, wyv.y, acc.y));
            acc.z = fmaf(pt.x, wxv.z, fmaf(pt.y, wyv.z, acc.z));
            acc.w = fmaf(pt.x, wxv.w, fmaf(pt.y, wyv.w, acc.w));
        }
        wx4 = *(const float4*)&sWx[u4];
        wy4 = *(const float4*)&sWy[u4];
        wn4 = *(const float4*)&sWn[u4];
    }

    // ---- phase C: one STG.128 per lane per output row ----
    // Row layout (512B): lanes 0-15 -> feats float4 (channels 4l..4l+3),
    // lanes 16-31 -> relu float4 (channels 64+4(l-16)..). Address = row + lane*16B.
    float4* __restrict__ row4 = out + (size_t)g * (OUT_FLOATS_PER_G / 4) + lane;
    const float4* __restrict__ fb4 = feats + (size_t)b * NPTS * 16;

    float4 f;
    if (!mlp) {
        const int i0 = __float_as_int(pts[warp][0].w);
        f = __ldcs(fb4 + i0 * 16 + lane);
    }

    #pragma unroll 1
    for (int j = 0; j < K1V; j++) {
        float4 fn;
        if (j + 1 < K1V && !mlp) {
            const int iin = __float_as_int(pts[warp][j + 1].w);
            fn = __ldcs(fb4 + iin * 16 + lane);
        }

        float4 sv;
        if (mlp) {
            const float4 pt = pts[warp][j];                     // LDS broadcast
            sv.x = fmaxf(fmaf(pt.z, wn4.x, fmaf(pt.y, wy4.x, fmaf(pt.x, wx4.x, acc.x))), 0.f);
            sv.y = fmaxf(fmaf(pt.z, wn4.y, fmaf(pt.y, wy4.y, fmaf(pt.x, wx4.y, acc.y))), 0.f);
            sv.z = fmaxf(fmaf(pt.z, wn4.z, fmaf(pt.y, wy4.z, fmaf(pt.x, wx4.z, acc.z))), 0.f);
            sv.w = fmaxf(fmaf(pt.z, wn4.w, fmaf(pt.y, wy4.w, fmaf(pt.x, wx4.w, acc.w))), 0.f);
        } else {
            sv = f;
        }

        __stcs(row4, sv);
        row4 += 32;
        f = fn;
    }
}

extern "C" void kernel_launch(void* const* d_in, const int* in_sizes, int n_in,
                              void* d_out, int out_size) {
    const float2* pc    = (const float2*)d_in[0];
    const float4* feats = (const float4*)d_in[1];
    const int*    nidx  = (const int*)d_in[2];
    const float*  W     = (const float*)d_in[3];
    const float*  bvec  = (const float*)d_in[4];

    float* out = (float*)d_out;
    // ggf tensor is concatenated after the main output
    float2* ggf = (float2*)(out + (size_t)BN * OUT_FLOATS_PER_G);

    locse_kernel<<<BN / WARPS, 256>>>(pc, feats, nidx, W, bvec,
                                      (float4*)out, ggf);
}

// round 7
// speedup vs baseline: 1.1414x; 1.1414x over previous
#include <cuda_runtime.h>

// LocSE fused kernel for GB300.
// Shapes (fixed): B=4, N=16384, DIMS=2, K1=17, UNITS=128, CH=53.
// Factorization: the (17 x 53) @ (53 x 64) per-neighborhood matmul
// = one shared 34-dim projection S[u] + a rank-3 per-j term.
// R7: R5 structure (no lane split) + launch_bounds(256,7) reg diet,
// ping-pong unroll-2 phase C (no pipeline MOVs), precomputed feats offsets.

#define NPTS   16384
#define BN     65536          // B*N
#define K1V    17
#define WARPS  8
#define OUT_FLOATS_PER_G 2176 // 17*128

__global__ __launch_bounds__(256, 7)
void locse_kernel(const float2* __restrict__ pc,      // (B,N) float2
                  const float2* __restrict__ feats,   // (B,N,32) float2 (64 floats)
                  const int*    __restrict__ nidx,    // (B,N,17)
                  const float*  __restrict__ W,       // (53,64)
                  const float*  __restrict__ bvec,    // (64,)
                  float2*       __restrict__ out,     // (B,N,17,64) float2
                  float2*       __restrict__ ggf)     // (B,N,1,2) as float2
{
    // S-projection weights, interleaved: sWs2[(2i+d)*32 + lane] holds
    // ( W[2+3i+d][2*lane], W[2+3i+d][2*lane+1] )
    __shared__ float2 sWs2[34 * 32];
    __shared__ float  sWx[64], sWy[64], sWn[64], sB[64];
    __shared__ float4 pts[WARPS][K1V];   // (x, y, norm, (ii*32)_as_float)

    const int tid = threadIdx.x;

    // ---- stage derived weights (once per block) ----
    if (tid < 64) {
        const int u = tid;
        float wx = W[u];          // W[0][u]
        float wy = W[64 + u];     // W[1][u]
        float wn = 0.f;
        #pragma unroll
        for (int i = 0; i < K1V; i++) {
            wx -= W[(2 + 3 * i) * 64 + u];
            wy -= W[(3 + 3 * i) * 64 + u];
            wn += W[(4 + 3 * i) * 64 + u];
        }
        sWx[u] = wx; sWy[u] = wy; sWn[u] = wn; sB[u] = bvec[u];
    }
    {
        float* sWsF = (float*)sWs2;
        #pragma unroll 1
        for (int t = tid; t < 34 * 64; t += 256) {
            const int c = t >> 6, u = t & 63;
            const int i = c >> 1, d = c & 1;
            sWsF[t] = W[(2 + 3 * i + d) * 64 + u];
        }
    }
    __syncthreads();

    const int lane = tid & 31, warp = tid >> 5;
    const unsigned g = blockIdx.x * WARPS + warp;   // neighborhood id in [0, BN)
    const unsigned b = g >> 14;                     // g / 16384
    const int* __restrict__ ip = nidx + (size_t)g * K1V;

    // ---- phase A: gather 17 points, norms; stash feats offset (ii*32) ----
    float x = 0.f, y = 0.f;
    if (lane < K1V) {
        const int ii = ip[lane];
        const float2 p = pc[(size_t)b * NPTS + ii];
        x = p.x; y = p.y;
        const float nrm = sqrtf(x * x + y * y);
        pts[warp][lane] = make_float4(x, y, nrm, __int_as_float(ii * 32));
    }
    __syncwarp();

    // ---- ggf: two-pass centered stats over 17 points (matches reference) ----
    float sx = x, sy = y;
    #pragma unroll
    for (int o = 16; o; o >>= 1) {
        sx += __shfl_xor_sync(0xffffffffu, sx, o);
        sy += __shfl_xor_sync(0xffffffffu, sy, o);
    }
    const float inv17 = 1.0f / 17.0f;
    const float mx = sx * inv17, my = sy * inv17;
    const float xc = (lane < K1V) ? (x - mx) : 0.f;
    const float yc = (lane < K1V) ? (y - my) : 0.f;
    float sxx = xc * xc, syy = yc * yc, sxy = xc * yc;
    #pragma unroll
    for (int o = 16; o; o >>= 1) {
        sxx += __shfl_xor_sync(0xffffffffu, sxx, o);
        syy += __shfl_xor_sync(0xffffffffu, syy, o);
        sxy += __shfl_xor_sync(0xffffffffu, sxy, o);
    }
    if (lane == 0) {
        const float vx = sxx * inv17, vy = syy * inv17, cov = sxy * inv17;
        const float m    = cov / (vx + 1e-8f);
        const float pear = cov / (sqrtf(vx * vy) + 1e-8f);
        __stcs(ggf + g, make_float2(m, 1.0f - pear));
    }

    // ---- phase B: shared projection S[u] (each lane owns u0=2*lane, u1=2*lane+1) ----
    float acc0 = sB[2 * lane], acc1 = sB[2 * lane + 1];
    #pragma unroll
    for (int i = 0; i < K1V; i++) {
        const float4 pt  = pts[warp][i];                 // LDS broadcast
        const float2 wxv = sWs2[(2 * i) * 32 + lane];
        const float2 wyv = sWs2[(2 * i + 1) * 32 + lane];
        acc0 = fmaf(pt.x, wxv.x, acc0);
        acc1 = fmaf(pt.x, wxv.y, acc1);
        acc0 = fmaf(pt.y, wyv.x, acc0);
        acc1 = fmaf(pt.y, wyv.y, acc1);
    }
    const float wx0 = sWx[2 * lane], wx1 = sWx[2 * lane + 1];
    const float wy0 = sWy[2 * lane], wy1 = sWy[2 * lane + 1];
    const float wn0 = sWn[2 * lane], wn1 = sWn[2 * lane + 1];

    // ---- phase C: ping-pong unroll-2, one feats LDG.64 + 2 STG.64 per j ----
    float2* __restrict__ outBase = out + (size_t)g * (OUT_FLOATS_PER_G / 2) + lane;
    const float2* __restrict__ fb = feats + (size_t)b * NPTS * 32 + lane;

    #define LDF(j) __ldcs(fb + __float_as_int(pts[warp][j].w))
    #define CST(j, fv) do {                                                   \
        const float4 pt = pts[warp][j];                                       \
        float r0 = fmaf(pt.z, wn0, fmaf(pt.y, wy0, fmaf(pt.x, wx0, acc0)));   \
        float r1 = fmaf(pt.z, wn1, fmaf(pt.y, wy1, fmaf(pt.x, wx1, acc1)));   \
        r0 = fmaxf(r0, 0.f); r1 = fmaxf(r1, 0.f);                             \
        float2* row = outBase + (j) * 64;                                     \
        __stcs(row, fv);                                                      \
        __stcs(row + 32, make_float2(r0, r1));                                \
    } while (0)

    float2 fa = LDF(0);
    #pragma unroll 1
    for (int j = 0; j < 16; j += 2) {
        float2 fc = LDF(j + 1);
        CST(j, fa);
        fa = LDF(j + 2);         // j+2 <= 16 always valid
        CST(j + 1, fc);
    }
    CST(16, fa);

    #undef LDF
    #undef CST
}

extern "C" void kernel_launch(void* const* d_in, const int* in_sizes, int n_in,
                              void* d_out, int out_size) {
    const float2* pc    = (const float2*)d_in[0];
    const float2* feats = (const float2*)d_in[1];
    const int*    nidx  = (const int*)d_in[2];
    const float*  W     = (const float*)d_in[3];
    const float*  bvec  = (const float*)d_in[4];

    float* out = (float*)d_out;
    // ggf tensor is concatenated after the main output
    float2* ggf = (float2*)(out + (size_t)BN * OUT_FLOATS_PER_G);

    locse_kernel<<<BN / WARPS, 256>>>(pc, feats, nidx, W, bvec,
                                      (float2*)out, ggf);
}

// round 8
// speedup vs baseline: 1.1519x; 1.0092x over previous
#include <cuda_runtime.h>

// LocSE fused kernel for GB300.
// Shapes (fixed): B=4, N=16384, DIMS=2, K1=17, UNITS=128, CH=53.
// Factorization: the (17 x 53) @ (53 x 64) per-neighborhood matmul
// = one shared 34-dim projection S[u] + a rank-3 per-j term.
// R8: L1-wavefront diet — single LDS.128 per j in phase C (ping-pong, no MOVs),
// single LDS.128 per i in phase B (float4-packed weights), occ target 7 CTAs/SM.

#define NPTS   16384
#define BN     65536          // B*N
#define K1V    17
#define WARPS  8
#define OUT_FLOATS_PER_G 2176 // 17*128

__global__ __launch_bounds__(256, 7)
void locse_kernel(const float2* __restrict__ pc,      // (B,N) float2
                  const float2* __restrict__ feats,   // (B,N,32) float2 (64 floats)
                  const int*    __restrict__ nidx,    // (B,N,17)
                  const float*  __restrict__ W,       // (53,64)
                  const float*  __restrict__ bvec,    // (64,)
                  float2*       __restrict__ out,     // (B,N,17,64) float2
                  float2*       __restrict__ ggf)     // (B,N,1,2) as float2
{
    // sW4[i*32 + lane] = ( W[2+3i][2l], W[2+3i][2l+1], W[3+3i][2l], W[3+3i][2l+1] )
    __shared__ float4 sW4[K1V * 32];
    __shared__ float  sWx[64], sWy[64], sWn[64], sB[64];
    __shared__ float4 pts[WARPS][K1V];   // (x, y, norm, (ii*32)_as_float)

    const int tid = threadIdx.x;

    // ---- stage derived weights (once per block) ----
    if (tid < 64) {
        const int u = tid;
        float wx = W[u];          // W[0][u]
        float wy = W[64 + u];     // W[1][u]
        float wn = 0.f;
        #pragma unroll
        for (int i = 0; i < K1V; i++) {
            wx -= W[(2 + 3 * i) * 64 + u];
            wy -= W[(3 + 3 * i) * 64 + u];
            wn += W[(4 + 3 * i) * 64 + u];
        }
        sWx[u] = wx; sWy[u] = wy; sWn[u] = wn; sB[u] = bvec[u];
    }
    {
        float* sW4F = (float*)sW4;
        #pragma unroll 1
        for (int t = tid; t < K1V * 128; t += 256) {
            const int i = t >> 7;            // point index
            const int l = (t >> 2) & 31;     // lane
            const int c = t & 3;             // component
            const int row = (c < 2 ? 2 : 3) + 3 * i;
            const int col = 2 * l + (c & 1);
            sW4F[t] = W[row * 64 + col];
        }
    }
    __syncthreads();

    const int lane = tid & 31, warp = tid >> 5;
    const unsigned g = blockIdx.x * WARPS + warp;   // neighborhood id in [0, BN)
    const unsigned b = g >> 14;                     // g / 16384
    const int* __restrict__ ip = nidx + (size_t)g * K1V;

    // ---- phase A: gather 17 points, norms; stash feats offset (ii*32) ----
    float x = 0.f, y = 0.f;
    if (lane < K1V) {
        const int ii = ip[lane];
        const float2 p = pc[(size_t)b * NPTS + ii];
        x = p.x; y = p.y;
        const float nrm = sqrtf(x * x + y * y);
        pts[warp][lane] = make_float4(x, y, nrm, __int_as_float(ii * 32));
    }
    __syncwarp();

    // ---- ggf: two-pass centered stats over 17 points (matches reference) ----
    float sx = x, sy = y;
    #pragma unroll
    for (int o = 16; o; o >>= 1) {
        sx += __shfl_xor_sync(0xffffffffu, sx, o);
        sy += __shfl_xor_sync(0xffffffffu, sy, o);
    }
    const float inv17 = 1.0f / 17.0f;
    const float mx = sx * inv17, my = sy * inv17;
    const float xc = (lane < K1V) ? (x - mx) : 0.f;
    const float yc = (lane < K1V) ? (y - my) : 0.f;
    float sxx = xc * xc, syy = yc * yc, sxy = xc * yc;
    #pragma unroll
    for (int o = 16; o; o >>= 1) {
        sxx += __shfl_xor_sync(0xffffffffu, sxx, o);
        syy += __shfl_xor_sync(0xffffffffu, syy, o);
        sxy += __shfl_xor_sync(0xffffffffu, sxy, o);
    }
    if (lane == 0) {
        const float vx = sxx * inv17, vy = syy * inv17, cov = sxy * inv17;
        const float m    = cov / (vx + 1e-8f);
        const float pear = cov / (sqrtf(vx * vy) + 1e-8f);
        __stcs(ggf + g, make_float2(m, 1.0f - pear));
    }

    // ---- phase B: shared projection S[u]; one LDS.128 (pt) + one LDS.128 (w) per i ----
    float acc0 = sB[2 * lane], acc1 = sB[2 * lane + 1];
    #pragma unroll
    for (int i = 0; i < K1V; i++) {
        const float4 pt = pts[warp][i];                  // LDS broadcast
        const float4 w  = sW4[i * 32 + lane];
        acc0 = fmaf(pt.x, w.x, acc0);
        acc1 = fmaf(pt.x, w.y, acc1);
        acc0 = fmaf(pt.y, w.z, acc0);
        acc1 = fmaf(pt.y, w.w, acc1);
    }
    const float wx0 = sWx[2 * lane], wx1 = sWx[2 * lane + 1];
    const float wy0 = sWy[2 * lane], wy1 = sWy[2 * lane + 1];
    const float wn0 = sWn[2 * lane], wn1 = sWn[2 * lane + 1];

    // ---- phase C: ping-pong unroll-2, ONE LDS.128 per j (pt reused for gather addr) ----
    float2* __restrict__ outBase = out + (size_t)g * (OUT_FLOATS_PER_G / 2) + lane;
    const float2* __restrict__ fb = feats + (size_t)b * NPTS * 32 + lane;

    #define CST(j, pt, fv) do {                                               \
        float r0 = fmaf((pt).z, wn0, fmaf((pt).y, wy0, fmaf((pt).x, wx0, acc0))); \
        float r1 = fmaf((pt).z, wn1, fmaf((pt).y, wy1, fmaf((pt).x, wx1, acc1))); \
        r0 = fmaxf(r0, 0.f); r1 = fmaxf(r1, 0.f);                             \
        float2* row = outBase + (j) * 64;                                     \
        __stcs(row, fv);                                                      \
        __stcs(row + 32, make_float2(r0, r1));                                \
    } while (0)

    float4 pa = pts[warp][0];
    float2 fa = __ldcs(fb + __float_as_int(pa.w));
    #pragma unroll 1
    for (int j = 0; j < 16; j += 2) {
        float4 pb2 = pts[warp][j + 1];
        float2 fb2 = __ldcs(fb + __float_as_int(pb2.w));
        CST(j, pa, fa);
        pa = pts[warp][j + 2];               // j+2 <= 16 always valid
        fa = __ldcs(fb + __float_as_int(pa.w));
        CST(j + 1, pb2, fb2);
    }
    CST(16, pa, fa);

    #undef CST
}

extern "C" void kernel_launch(void* const* d_in, const int* in_sizes, int n_in,
                              void* d_out, int out_size) {
    const float2* pc    = (const float2*)d_in[0];
    const float2* feats = (const float2*)d_in[1];
    const int*    nidx  = (const int*)d_in[2];
    const float*  W     = (const float*)d_in[3];
    const float*  bvec  = (const float*)d_in[4];

    float* out = (float*)d_out;
    // ggf tensor is concatenated after the main output
    float2* ggf = (float2*)(out + (size_t)BN * OUT_FLOATS_PER_G);

    locse_kernel<<<BN / WARPS, 256>>>(pc, feats, nidx, W, bvec,
                                      (float2*)out, ggf);
}